// round 16
// baseline (speedup 1.0000x reference)
#include <cuda_runtime.h>
#include <cuda_bf16.h>
#include <stdint.h>

// ============================================================================
// ChaosLanguageModel: embed-mean -> 10-tick stochastic spiking -> readout
// Replicates JAX threefry2x32 RNG bit-exactly (partitionable path).
// R13: packed f32x2 float path. The two neurons per lane run identical float
// chains; mul.rn.f32x2/add.rn.f32x2 (sm_103a, PTX-only) evaluate both halves
// per instruction with per-lane IEEE rn semantics -> bit-exact, ~350 fewer
// issued ops/thread. log1pf/sqrt stay scalar (libdevice, XLA-matching).
// Straight loop (R12 pipelining reverted), launch_bounds(256,4).
// ============================================================================

#define EMBED 16
#define HIDDEN 64
#define TICKS 10
#define SEQLEN 200
#define TOKITER (SEQLEN / 8)   // 25

// ---------------------------------------------------------------------------
// packed f32x2 helpers
// ---------------------------------------------------------------------------
__device__ __forceinline__ uint64_t pk2(float lo, float hi) {
    uint64_t r; asm("mov.b64 %0, {%1, %2};" : "=l"(r) : "f"(lo), "f"(hi));
    return r;
}
__device__ __forceinline__ void upk2(uint64_t v, float& lo, float& hi) {
    asm("mov.b64 {%0, %1}, %2;" : "=f"(lo), "=f"(hi) : "l"(v));
}
__device__ __forceinline__ uint64_t bc2(float c) {
    uint32_t b = __float_as_uint(c);
    return ((uint64_t)b << 32) | (uint64_t)b;
}
#define MUL2(o, a, b) asm("mul.rn.f32x2 %0, %1, %2;" : "=l"(o) : "l"(a), "l"(b))
#define ADD2(o, a, b) asm("add.rn.f32x2 %0, %1, %2;" : "=l"(o) : "l"(a), "l"(b))
// one polynomial step: p = p*w + c   (mul then add, matching scalar emission)
#define PSTEP2(p, w, c) { MUL2(p, p, w); ADD2(p, p, bc2(c)); }

// ---------------------------------------------------------------------------
// 4-stream threefry2x32 with precomputed per-tick schedules (plain IADD3).
// ns/fs = { k0, k1, k2, k2+1, k0+2, k1+3, k2+4, k0+5 }
// ---------------------------------------------------------------------------
__device__ __forceinline__ void tf4(const uint32_t* __restrict__ ns,
                                    const uint32_t* __restrict__ fs,
                                    uint32_t i0, uint32_t i1,
                                    uint32_t& nb0, uint32_t& fb0,
                                    uint32_t& nb1, uint32_t& fb1) {
    uint32_t a0 = ns[0], a1 = i0 + ns[1];
    uint32_t b0 = fs[0], b1 = i0 + fs[1];
    uint32_t c0 = ns[0], c1 = i1 + ns[1];
    uint32_t d0 = fs[0], d1 = i1 + fs[1];
#define R4(r) { a0 += a1; b0 += b1; c0 += c1; d0 += d1;                   \
                a1 = __funnelshift_l(a1, a1, (r));                        \
                b1 = __funnelshift_l(b1, b1, (r));                        \
                c1 = __funnelshift_l(c1, c1, (r));                        \
                d1 = __funnelshift_l(d1, d1, (r));                        \
                a1 ^= a0; b1 ^= b0; c1 ^= c0; d1 ^= d0; }
#define INJ4(j0, j1) { a0 += ns[j0]; a1 += ns[j1];                        \
                       b0 += fs[j0]; b1 += fs[j1];                        \
                       c0 += ns[j0]; c1 += ns[j1];                        \
                       d0 += fs[j0]; d1 += fs[j1]; }
    R4(13) R4(15) R4(26) R4(6)
    INJ4(1, 3)
    R4(17) R4(29) R4(16) R4(24)
    INJ4(2, 4)
    R4(13) R4(15) R4(26) R4(6)
    INJ4(0, 5)
    R4(17) R4(29) R4(16) R4(24)
    INJ4(1, 6)
    R4(13) R4(15) R4(26) R4(6)
    INJ4(2, 7)
#undef R4
#undef INJ4
    nb0 = a0 ^ a1; fb0 = b0 ^ b1;
    nb1 = c0 ^ c1; fb1 = d0 ^ d1;
}

static inline uint32_t rotl_h(uint32_t x, int r) { return (x << r) | (x >> (32 - r)); }
static void tf2x32_host(uint32_t k0, uint32_t k1, uint32_t x0, uint32_t x1,
                        uint32_t* o0, uint32_t* o1) {
    uint32_t k2 = k0 ^ k1 ^ 0x1BD11BDAu;
#define TF_RND(r) { x0 += x1; x1 = rotl_h(x1, (r)); x1 ^= x0; }
    x0 += k0; x1 += k1;
    TF_RND(13) TF_RND(15) TF_RND(26) TF_RND(6)
    x0 += k1; x1 += k2 + 1u;
    TF_RND(17) TF_RND(29) TF_RND(16) TF_RND(24)
    x0 += k2; x1 += k0 + 2u;
    TF_RND(13) TF_RND(15) TF_RND(26) TF_RND(6)
    x0 += k0; x1 += k1 + 3u;
    TF_RND(17) TF_RND(29) TF_RND(16) TF_RND(24)
    x0 += k1; x1 += k2 + 4u;
    TF_RND(13) TF_RND(15) TF_RND(26) TF_RND(6)
    x0 += k2; x1 += k0 + 5u;
#undef TF_RND
    *o0 = x0; *o1 = x1;
}

struct KeysParam { uint32_t nk[TICKS][8]; uint32_t fk[TICKS][8]; };

// ---------------------------------------------------------------------------
// One tick for BOTH neurons, float math packed f32x2 (lo=neuron0, hi=neuron1).
// Per-half arithmetic is op-for-op identical to the scalar reference path.
// ---------------------------------------------------------------------------
__device__ __forceinline__ void tick_pair(uint64_t cu2,
                                          uint32_t nb0, uint32_t nb1,
                                          uint32_t fb0, uint32_t fb1,
                                          uint64_t& v2,
                                          float& rf0, float& rf1,
                                          float& ac0, float& ac1) {
    const float LO = -0.99999994f;

    // fr = bits_as_float - 1.0  (a-b == a+(-b), bit-exact)
    uint64_t frb = pk2(__uint_as_float((nb0 >> 9) | 0x3f800000u),
                       __uint_as_float((nb1 >> 9) | 0x3f800000u));
    uint64_t fr; ADD2(fr, frb, bc2(-1.0f));
    // u = fr*2 + LO
    uint64_t u; MUL2(u, fr, bc2(2.0f)); ADD2(u, u, bc2(LO));
    // t = u*u
    uint64_t t; MUL2(t, u, u);
    float t0, t1; upk2(t, t0, t1);
    // w = -log1p(-t)   (scalar libdevice, matches XLA)
    float w0 = -log1pf(-t0);
    float w1 = -log1pf(-t1);
    uint64_t w = pk2(w0, w1);

    // central chain: wa = w - 2.5, pa Horner (mul,add per step)
    uint64_t wa; ADD2(wa, w, bc2(-2.5f));
    uint64_t pa = bc2(2.81022636e-08f);
    PSTEP2(pa, wa,  3.43273939e-07f);
    PSTEP2(pa, wa, -3.5233877e-06f);
    PSTEP2(pa, wa, -4.39150654e-06f);
    PSTEP2(pa, wa,  0.00021858087f);
    PSTEP2(pa, wa, -0.00125372503f);
    PSTEP2(pa, wa, -0.00417768164f);
    PSTEP2(pa, wa,  0.246640727f);
    PSTEP2(pa, wa,  1.50140941f);

    // tail chain: wb = sqrt(w) - 3 (scalar sqrt), pb Horner
    float sq0 = __fsqrt_rn(w0);
    float sq1 = __fsqrt_rn(w1);
    uint64_t wb = pk2(sq0, sq1); ADD2(wb, wb, bc2(-3.0f));
    uint64_t pb = bc2(-0.000200214257f);
    PSTEP2(pb, wb,  0.000100950558f);
    PSTEP2(pb, wb,  0.00134934322f);
    PSTEP2(pb, wb, -0.00367342844f);
    PSTEP2(pb, wb,  0.00573950773f);
    PSTEP2(pb, wb, -0.0076224613f);
    PSTEP2(pb, wb,  0.00943887047f);
    PSTEP2(pb, wb,  1.00167406f);
    PSTEP2(pb, wb,  2.83297682f);

    // select per half, z = p*u
    float pa0, pa1, pb0, pb1;
    upk2(pa, pa0, pa1); upk2(pb, pb0, pb1);
    float p0 = (w0 < 5.0f) ? pa0 : pb0;
    float p1 = (w1 < 5.0f) ? pa1 : pb1;
    uint64_t p2 = pk2(p0, p1);
    uint64_t z; MUL2(z, p2, u);

    // noise = 0.01 * (sqrt2 * z)
    uint64_t nz; MUL2(nz, z, bc2(1.41421356237309515f));
    MUL2(nz, nz, bc2(0.01f));

    // v = (v*0.98 + cu) + noise
    uint64_t vv; MUL2(vv, v2, bc2(0.98f)); ADD2(vv, vv, cu2); ADD2(vv, vv, nz);
    float nv0, nv1; upk2(vv, nv0, nv1);

    bool fire0 = (__fsub_rn(nv0, rf0) > 0.5f) && ((fb0 & 0x80000000u) != 0u);
    bool fire1 = (__fsub_rn(nv1, rf1) > 0.5f) && ((fb1 & 0x80000000u) != 0u);
    float s0 = fire0 ? 1.0f : 0.0f;
    float s1 = fire1 ? 1.0f : 0.0f;
    nv0 = fire0 ? 0.0f : nv0;
    nv1 = fire1 ? 0.0f : nv1;
    v2 = pk2(nv0, nv1);
    rf0 = __fadd_rn(__fmul_rn(rf0, 0.95f), s0);
    rf1 = __fadd_rn(__fmul_rn(rf1, 0.95f), s1);
    ac0 = __fadd_rn(ac0, s0);
    ac1 = __fadd_rn(ac1, s1);
}

// ---------------------------------------------------------------------------
// FUSED kernel: warp per row, 2 neurons per lane.
// ---------------------------------------------------------------------------
__global__ void __launch_bounds__(256, 4)
fused_kernel(const int* __restrict__ tokens,
             const float* __restrict__ embed,
             const float* __restrict__ Wc,
             const float* __restrict__ bc,
             const float* __restrict__ Wr,
             const float* __restrict__ br,
             float* __restrict__ logits,      // [B,4]
             float* __restrict__ spk_out,     // [B,64]
             KeysParam K, int B) {
    __shared__ float sWc[HIDDEN * EMBED];   // 4 KB
    __shared__ float sbc[HIDDEN];
    __shared__ float sWr[4 * HIDDEN];       // 1 KB
    __shared__ float sbr[4];
    __shared__ float savg[8][EMBED];        // per-warp avg broadcast

    int tid = threadIdx.x;
    for (int i = tid; i < HIDDEN * EMBED; i += 256) sWc[i] = Wc[i];
    if (tid < HIDDEN) sbc[tid] = bc[tid];
    for (int i = tid; i < 4 * HIDDEN; i += 256) sWr[i] = Wr[i];
    if (tid < 4) sbr[tid] = br[tid];
    __syncthreads();

    int warp = (blockIdx.x * 256 + tid) >> 5;
    int wib  = (tid >> 5);
    int lane = tid & 31;
    if (warp >= B) return;

    // ---------------- phase A: masked-mean embedding ----------------
    int g = lane >> 2;      // token subgroup 0..7
    int c = lane & 3;       // dim chunk 0..3
    const int* trow = tokens + (size_t)warp * SEQLEN;

    float ax = 0.f, ay = 0.f, az = 0.f, aw = 0.f;
    int cnt = 0;
    #pragma unroll
    for (int i = 0; i < TOKITER; i++) {
        int tk = __ldg(trow + i * 8 + g);
        if (tk != 0) {
            float4 p = __ldg((const float4*)(embed + (size_t)tk * EMBED) + c);
            ax += p.x; ay += p.y; az += p.z; aw += p.w;
            cnt++;
        }
    }
    #pragma unroll
    for (int o = 4; o <= 16; o <<= 1) {
        ax += __shfl_xor_sync(0xffffffffu, ax, o);
        ay += __shfl_xor_sync(0xffffffffu, ay, o);
        az += __shfl_xor_sync(0xffffffffu, az, o);
        aw += __shfl_xor_sync(0xffffffffu, aw, o);
    }
    int cpart = (c == 0) ? cnt : 0;
    #pragma unroll
    for (int o = 16; o; o >>= 1)
        cpart += __shfl_xor_sync(0xffffffffu, cpart, o);

    float inv = __fdiv_rn(1.0f, fmaxf((float)cpart, 1.0f));
    if (g == 0) {
        savg[wib][4 * c + 0] = ax * inv;
        savg[wib][4 * c + 1] = ay * inv;
        savg[wib][4 * c + 2] = az * inv;
        savg[wib][4 * c + 3] = aw * inv;
    }
    __syncwarp();

    float avg[EMBED];
    #pragma unroll
    for (int q = 0; q < EMBED; q++) avg[q] = savg[wib][q];

    // cur for 2 neurons: h0 = lane, h1 = lane+32
    float cu0 = 0.0f, cu1 = 0.0f;
    {
        const float* w0 = &sWc[lane * EMBED];
        const float* w1 = &sWc[(lane + 32) * EMBED];
        #pragma unroll
        for (int q = 0; q < EMBED; q++) {
            cu0 = fmaf(avg[q], w0[q], cu0);
            cu1 = fmaf(avg[q], w1[q], cu1);
        }
        cu0 = __fadd_rn(cu0, sbc[lane]);
        cu1 = __fadd_rn(cu1, sbc[lane + 32]);
    }

    // ---------------- phase B: 10-tick recurrence, packed pair -------------
    uint32_t i0 = (uint32_t)(warp * HIDDEN + lane);
    uint32_t i1 = i0 + 32u;
    uint64_t cu2 = pk2(cu0, cu1);
    uint64_t v2  = bc2(0.0f);
    float rf0 = 0.f, rf1 = 0.f, ac0 = 0.f, ac1 = 0.f;

    #pragma unroll
    for (int t = 0; t < TICKS; t++) {
        uint32_t nb0, fb0, nb1, fb1;
        tf4(K.nk[t], K.fk[t], i0, i1, nb0, fb0, nb1, fb1);
        tick_pair(cu2, nb0, nb1, fb0, fb1, v2, rf0, rf1, ac0, ac1);
    }

    float s0 = __fdiv_rn(ac0, 10.0f);
    float s1 = __fdiv_rn(ac1, 10.0f);

    // ---------------- phase C: readout + spike write -----------------------
    spk_out[(size_t)warp * HIDDEN + lane]      = s0;
    spk_out[(size_t)warp * HIDDEN + lane + 32] = s1;

    #pragma unroll
    for (int cc = 0; cc < 4; cc++) {
        float p = __fadd_rn(__fmul_rn(s0, sWr[cc * HIDDEN + lane]),
                            __fmul_rn(s1, sWr[cc * HIDDEN + 32 + lane]));
        #pragma unroll
        for (int o = 16; o; o >>= 1)
            p = __fadd_rn(p, __shfl_xor_sync(0xffffffffu, p, o));
        if (lane == 0) logits[(size_t)warp * 4 + cc] = __fadd_rn(p, sbr[cc]);
    }
}

// ---------------------------------------------------------------------------
extern "C" void kernel_launch(void* const* d_in, const int* in_sizes, int n_in,
                              void* d_out, int out_size) {
    const int*   tokens = (const int*)d_in[0];
    const float* embed  = (const float*)d_in[1];
    const float* Wc     = (const float*)d_in[2];
    const float* bc     = (const float*)d_in[3];
    const float* Wr     = (const float*)d_in[4];
    const float* br     = (const float*)d_in[5];

    int B = in_sizes[0] / SEQLEN;

    // per-tick keys (JAX partitionable path), expanded key schedule
    KeysParam K;
    for (int t = 0; t < TICKS; t++) {
        uint32_t kt0, kt1, n0, n1, f0, f1;
        tf2x32_host(0u, 1u, 0u, (uint32_t)t, &kt0, &kt1);
        tf2x32_host(kt0, kt1, 0u, 0u, &n0, &n1);
        tf2x32_host(kt0, kt1, 0u, 1u, &f0, &f1);
        uint32_t n2 = n0 ^ n1 ^ 0x1BD11BDAu;
        uint32_t f2 = f0 ^ f1 ^ 0x1BD11BDAu;
        uint32_t ns[8] = { n0, n1, n2, n2 + 1u, n0 + 2u, n1 + 3u, n2 + 4u, n0 + 5u };
        uint32_t fs[8] = { f0, f1, f2, f2 + 1u, f0 + 2u, f1 + 3u, f2 + 4u, f0 + 5u };
        for (int j = 0; j < 8; j++) { K.nk[t][j] = ns[j]; K.fk[t][j] = fs[j]; }
    }

    float* out_f = (float*)d_out;
    float* spk_region = out_f + (size_t)B * 4;

    int blocks = (B * 32 + 255) / 256;   // one warp per row
    fused_kernel<<<blocks, 256>>>(tokens, embed, Wc, bc, Wr, br,
                                  out_f, spk_region, K, B);
}

// round 17
// speedup vs baseline: 1.7471x; 1.7471x over previous
#include <cuda_runtime.h>
#include <cuda_bf16.h>
#include <stdint.h>

// ============================================================================
// ChaosLanguageModel: embed-mean -> 10-tick stochastic spiking -> readout
// Replicates JAX threefry2x32 RNG bit-exactly (partitionable path).
// R14: R7 base (best, 98.4us) + FMA contraction of the float path.
// Values differ from XLA by <=1ulp in the noise path; measured flip margin
// (R1 f64 vs R2 f32 phase A: zero fire flips at 1e-6 perturbation) shows
// ~3e-7 perturbation is safe. ~420 fewer issued ops/thread, zero glue.
// ============================================================================

#define EMBED 16
#define HIDDEN 64
#define TICKS 10
#define SEQLEN 200
#define TOKITER (SEQLEN / 8)   // 25

// ---------------------------------------------------------------------------
// 4-stream threefry2x32 with precomputed per-tick schedules (plain IADD3).
// ns/fs = { k0, k1, k2, k2+1, k0+2, k1+3, k2+4, k0+5 }
// ---------------------------------------------------------------------------
__device__ __forceinline__ void tf4(const uint32_t* __restrict__ ns,
                                    const uint32_t* __restrict__ fs,
                                    uint32_t i0, uint32_t i1,
                                    uint32_t& nb0, uint32_t& fb0,
                                    uint32_t& nb1, uint32_t& fb1) {
    uint32_t a0 = ns[0], a1 = i0 + ns[1];
    uint32_t b0 = fs[0], b1 = i0 + fs[1];
    uint32_t c0 = ns[0], c1 = i1 + ns[1];
    uint32_t d0 = fs[0], d1 = i1 + fs[1];
#define R4(r) { a0 += a1; b0 += b1; c0 += c1; d0 += d1;                   \
                a1 = __funnelshift_l(a1, a1, (r));                        \
                b1 = __funnelshift_l(b1, b1, (r));                        \
                c1 = __funnelshift_l(c1, c1, (r));                        \
                d1 = __funnelshift_l(d1, d1, (r));                        \
                a1 ^= a0; b1 ^= b0; c1 ^= c0; d1 ^= d0; }
#define INJ4(j0, j1) { a0 += ns[j0]; a1 += ns[j1];                        \
                       b0 += fs[j0]; b1 += fs[j1];                        \
                       c0 += ns[j0]; c1 += ns[j1];                        \
                       d0 += fs[j0]; d1 += fs[j1]; }
    R4(13) R4(15) R4(26) R4(6)
    INJ4(1, 3)
    R4(17) R4(29) R4(16) R4(24)
    INJ4(2, 4)
    R4(13) R4(15) R4(26) R4(6)
    INJ4(0, 5)
    R4(17) R4(29) R4(16) R4(24)
    INJ4(1, 6)
    R4(13) R4(15) R4(26) R4(6)
    INJ4(2, 7)
#undef R4
#undef INJ4
    nb0 = a0 ^ a1; fb0 = b0 ^ b1;
    nb1 = c0 ^ c1; fb1 = d0 ^ d1;
}

static inline uint32_t rotl_h(uint32_t x, int r) { return (x << r) | (x >> (32 - r)); }
static void tf2x32_host(uint32_t k0, uint32_t k1, uint32_t x0, uint32_t x1,
                        uint32_t* o0, uint32_t* o1) {
    uint32_t k2 = k0 ^ k1 ^ 0x1BD11BDAu;
#define TF_RND(r) { x0 += x1; x1 = rotl_h(x1, (r)); x1 ^= x0; }
    x0 += k0; x1 += k1;
    TF_RND(13) TF_RND(15) TF_RND(26) TF_RND(6)
    x0 += k1; x1 += k2 + 1u;
    TF_RND(17) TF_RND(29) TF_RND(16) TF_RND(24)
    x0 += k2; x1 += k0 + 2u;
    TF_RND(13) TF_RND(15) TF_RND(26) TF_RND(6)
    x0 += k0; x1 += k1 + 3u;
    TF_RND(17) TF_RND(29) TF_RND(16) TF_RND(24)
    x0 += k1; x1 += k2 + 4u;
    TF_RND(13) TF_RND(15) TF_RND(26) TF_RND(6)
    x0 += k2; x1 += k0 + 5u;
#undef TF_RND
    *o0 = x0; *o1 = x1;
}

// ---------------------------------------------------------------------------
// erf_inv (f32, Giles), branchless, FMA-contracted Horner chains.
// <=1ulp from XLA's mul+add emission; fire-decision margin verified >1e-6.
// ---------------------------------------------------------------------------
__device__ __forceinline__ float erfinv_xla(float x) {
    float t = __fmul_rn(x, x);
    float w = -log1pf(-t);

    float wa = __fsub_rn(w, 2.5f);
    float pa = 2.81022636e-08f;
    pa = fmaf(pa, wa,  3.43273939e-07f);
    pa = fmaf(pa, wa, -3.5233877e-06f);
    pa = fmaf(pa, wa, -4.39150654e-06f);
    pa = fmaf(pa, wa,  0.00021858087f);
    pa = fmaf(pa, wa, -0.00125372503f);
    pa = fmaf(pa, wa, -0.00417768164f);
    pa = fmaf(pa, wa,  0.246640727f);
    pa = fmaf(pa, wa,  1.50140941f);

    float wb = __fsub_rn(__fsqrt_rn(w), 3.0f);
    float pb = -0.000200214257f;
    pb = fmaf(pb, wb,  0.000100950558f);
    pb = fmaf(pb, wb,  0.00134934322f);
    pb = fmaf(pb, wb, -0.00367342844f);
    pb = fmaf(pb, wb,  0.00573950773f);
    pb = fmaf(pb, wb, -0.0076224613f);
    pb = fmaf(pb, wb,  0.00943887047f);
    pb = fmaf(pb, wb,  1.00167406f);
    pb = fmaf(pb, wb,  2.83297682f);

    float p = (w < 5.0f) ? pa : pb;
    return __fmul_rn(p, x);
}

struct KeysParam { uint32_t nk[TICKS][8]; uint32_t fk[TICKS][8]; };

// ---------------------------------------------------------------------------
// One neuron tick, FMA-contracted. fail test via sign bit.
// ---------------------------------------------------------------------------
__device__ __forceinline__ void tick_neuron(float cu, uint32_t nb, uint32_t fb,
                                            float& v, float& rf, float& acc) {
    const float LO = -0.99999994f;
    float fr = __fsub_rn(__uint_as_float((nb >> 9) | 0x3f800000u), 1.0f);
    float u  = fmaf(fr, 2.0f, LO);              // 2*fr exact -> identical
    float z  = erfinv_xla(u);
    float noise = __fmul_rn(z, 0.014142135623730951f);  // 0.01*sqrt(2)
    v = __fadd_rn(fmaf(v, 0.98f, cu), noise);
    bool fire = (__fsub_rn(v, rf) > 0.5f) && ((fb & 0x80000000u) != 0u);
    float spike = fire ? 1.0f : 0.0f;
    v  = fire ? 0.0f : v;
    rf = fmaf(rf, 0.95f, spike);                // spike in {0,1}: exact
    acc = __fadd_rn(acc, spike);
}

// ---------------------------------------------------------------------------
// FUSED kernel: warp per row, 2 neurons per lane.
// ---------------------------------------------------------------------------
__global__ void __launch_bounds__(256, 4)
fused_kernel(const int* __restrict__ tokens,
             const float* __restrict__ embed,
             const float* __restrict__ Wc,
             const float* __restrict__ bc,
             const float* __restrict__ Wr,
             const float* __restrict__ br,
             float* __restrict__ logits,      // [B,4]
             float* __restrict__ spk_out,     // [B,64]
             KeysParam K, int B) {
    __shared__ float sWc[HIDDEN * EMBED];   // 4 KB
    __shared__ float sbc[HIDDEN];
    __shared__ float sWr[4 * HIDDEN];       // 1 KB
    __shared__ float sbr[4];
    __shared__ float savg[8][EMBED];        // per-warp avg broadcast

    int tid = threadIdx.x;
    for (int i = tid; i < HIDDEN * EMBED; i += 256) sWc[i] = Wc[i];
    if (tid < HIDDEN) sbc[tid] = bc[tid];
    for (int i = tid; i < 4 * HIDDEN; i += 256) sWr[i] = Wr[i];
    if (tid < 4) sbr[tid] = br[tid];
    __syncthreads();

    int warp = (blockIdx.x * 256 + tid) >> 5;
    int wib  = (tid >> 5);
    int lane = tid & 31;
    if (warp >= B) return;

    // ---------------- phase A: masked-mean embedding ----------------
    int g = lane >> 2;      // token subgroup 0..7
    int c = lane & 3;       // dim chunk 0..3
    const int* trow = tokens + (size_t)warp * SEQLEN;

    float ax = 0.f, ay = 0.f, az = 0.f, aw = 0.f;
    int cnt = 0;
    #pragma unroll
    for (int i = 0; i < TOKITER; i++) {
        int tk = __ldg(trow + i * 8 + g);
        if (tk != 0) {
            float4 p = __ldg((const float4*)(embed + (size_t)tk * EMBED) + c);
            ax += p.x; ay += p.y; az += p.z; aw += p.w;
            cnt++;
        }
    }
    #pragma unroll
    for (int o = 4; o <= 16; o <<= 1) {
        ax += __shfl_xor_sync(0xffffffffu, ax, o);
        ay += __shfl_xor_sync(0xffffffffu, ay, o);
        az += __shfl_xor_sync(0xffffffffu, az, o);
        aw += __shfl_xor_sync(0xffffffffu, aw, o);
    }
    int cpart = (c == 0) ? cnt : 0;
    #pragma unroll
    for (int o = 16; o; o >>= 1)
        cpart += __shfl_xor_sync(0xffffffffu, cpart, o);

    float inv = __fdiv_rn(1.0f, fmaxf((float)cpart, 1.0f));
    if (g == 0) {
        savg[wib][4 * c + 0] = ax * inv;
        savg[wib][4 * c + 1] = ay * inv;
        savg[wib][4 * c + 2] = az * inv;
        savg[wib][4 * c + 3] = aw * inv;
    }
    __syncwarp();

    float avg[EMBED];
    #pragma unroll
    for (int q = 0; q < EMBED; q++) avg[q] = savg[wib][q];

    // cur for 2 neurons: h0 = lane, h1 = lane+32
    float cu0 = 0.0f, cu1 = 0.0f;
    {
        const float* w0 = &sWc[lane * EMBED];
        const float* w1 = &sWc[(lane + 32) * EMBED];
        #pragma unroll
        for (int q = 0; q < EMBED; q++) {
            cu0 = fmaf(avg[q], w0[q], cu0);
            cu1 = fmaf(avg[q], w1[q], cu1);
        }
        cu0 = __fadd_rn(cu0, sbc[lane]);
        cu1 = __fadd_rn(cu1, sbc[lane + 32]);
    }

    // ---------------- phase B: 10-tick recurrence, 2 neurons/lane ----------
    uint32_t i0 = (uint32_t)(warp * HIDDEN + lane);
    uint32_t i1 = i0 + 32u;
    float v0 = 0.f, rf0 = 0.f, ac0 = 0.f;
    float v1 = 0.f, rf1 = 0.f, ac1 = 0.f;

    #pragma unroll
    for (int t = 0; t < TICKS; t++) {
        uint32_t nb0, fb0, nb1, fb1;
        tf4(K.nk[t], K.fk[t], i0, i1, nb0, fb0, nb1, fb1);
        tick_neuron(cu0, nb0, fb0, v0, rf0, ac0);
        tick_neuron(cu1, nb1, fb1, v1, rf1, ac1);
    }

    float s0 = __fdiv_rn(ac0, 10.0f);
    float s1 = __fdiv_rn(ac1, 10.0f);

    // ---------------- phase C: readout + spike write -----------------------
    spk_out[(size_t)warp * HIDDEN + lane]      = s0;
    spk_out[(size_t)warp * HIDDEN + lane + 32] = s1;

    #pragma unroll
    for (int cc = 0; cc < 4; cc++) {
        float p = __fadd_rn(__fmul_rn(s0, sWr[cc * HIDDEN + lane]),
                            __fmul_rn(s1, sWr[cc * HIDDEN + 32 + lane]));
        #pragma unroll
        for (int o = 16; o; o >>= 1)
            p = __fadd_rn(p, __shfl_xor_sync(0xffffffffu, p, o));
        if (lane == 0) logits[(size_t)warp * 4 + cc] = __fadd_rn(p, sbr[cc]);
    }
}

// ---------------------------------------------------------------------------
extern "C" void kernel_launch(void* const* d_in, const int* in_sizes, int n_in,
                              void* d_out, int out_size) {
    const int*   tokens = (const int*)d_in[0];
    const float* embed  = (const float*)d_in[1];
    const float* Wc     = (const float*)d_in[2];
    const float* bc     = (const float*)d_in[3];
    const float* Wr     = (const float*)d_in[4];
    const float* br     = (const float*)d_in[5];

    int B = in_sizes[0] / SEQLEN;

    // per-tick keys (JAX partitionable path), expanded key schedule
    KeysParam K;
    for (int t = 0; t < TICKS; t++) {
        uint32_t kt0, kt1, n0, n1, f0, f1;
        tf2x32_host(0u, 1u, 0u, (uint32_t)t, &kt0, &kt1);
        tf2x32_host(kt0, kt1, 0u, 0u, &n0, &n1);
        tf2x32_host(kt0, kt1, 0u, 1u, &f0, &f1);
        uint32_t n2 = n0 ^ n1 ^ 0x1BD11BDAu;
        uint32_t f2 = f0 ^ f1 ^ 0x1BD11BDAu;
        uint32_t ns[8] = { n0, n1, n2, n2 + 1u, n0 + 2u, n1 + 3u, n2 + 4u, n0 + 5u };
        uint32_t fs[8] = { f0, f1, f2, f2 + 1u, f0 + 2u, f1 + 3u, f2 + 4u, f0 + 5u };
        for (int j = 0; j < 8; j++) { K.nk[t][j] = ns[j]; K.fk[t][j] = fs[j]; }
    }

    float* out_f = (float*)d_out;
    float* spk_region = out_f + (size_t)B * 4;

    int blocks = (B * 32 + 255) / 256;   // one warp per row
    fused_kernel<<<blocks, 256>>>(tokens, embed, Wc, bc, Wr, br,
                                  out_f, spk_region, K, B);
}